// round 1
// baseline (speedup 1.0000x reference)
#include <cuda_runtime.h>
#include <math.h>

#define B_ROWS 65536
#define NCOLS  512
#define EPSF   1e-8f

// pass1: 256 blocks x 256 threads = 2048 warps, 32 rows/warp
#define NB1 256
#define T1  256
#define W1  (NB1 * (T1 / 32))
#define RPW1 (B_ROWS / W1)

// pass3: 512 blocks x 256 threads = 4096 warps, 16 rows/warp
#define NB3 512
#define T3  256
#define W3  (NB3 * (T3 / 32))
#define RPW3 (B_ROWS / W3)

__device__ float g_sim[B_ROWS];
__device__ float g_amax[B_ROWS];
__device__ float g_ascale[B_ROWS];   // 1 / sum(exp(a - amax))
__device__ float g_t[B_ROWS];        // third-order entropy per row
__device__ float g_part[NB1 * NCOLS];
__device__ float g_colsum[NCOLS];

// ---------------------------------------------------------------------------
// Pass 1: per-row softmax of anchors & neighbors, sim = <a_prob, p_prob>,
// per-block partial column-sums of a_prob. One warp per row, float4 loads.
// Thread `lane` owns columns {4*lane + 128*k + c : k,c in 0..3}.
// ---------------------------------------------------------------------------
__global__ __launch_bounds__(T1) void scan_pass1(const float* __restrict__ A,
                                                 const float* __restrict__ P) {
    __shared__ float sbuf[T1 / 32][NCOLS];
    const int lane = threadIdx.x & 31;
    const int w    = threadIdx.x >> 5;
    const int wg   = blockIdx.x * (T1 >> 5) + w;

    float csum[16];
#pragma unroll
    for (int m = 0; m < 16; ++m) csum[m] = 0.f;

    for (int it = 0; it < RPW1; ++it) {
        const int row = wg + it * W1;
        const float4* a4 = reinterpret_cast<const float4*>(A) + (size_t)row * (NCOLS / 4);
        const float4* p4 = reinterpret_cast<const float4*>(P) + (size_t)row * (NCOLS / 4);

        float a[16], p[16];
#pragma unroll
        for (int k = 0; k < 4; ++k) {
            float4 v = a4[lane + 32 * k];
            a[4 * k + 0] = v.x; a[4 * k + 1] = v.y; a[4 * k + 2] = v.z; a[4 * k + 3] = v.w;
            float4 u = p4[lane + 32 * k];
            p[4 * k + 0] = u.x; p[4 * k + 1] = u.y; p[4 * k + 2] = u.z; p[4 * k + 3] = u.w;
        }

        float amax = a[0], pmax = p[0];
#pragma unroll
        for (int m = 1; m < 16; ++m) {
            amax = fmaxf(amax, a[m]);
            pmax = fmaxf(pmax, p[m]);
        }
#pragma unroll
        for (int o = 16; o; o >>= 1) {
            amax = fmaxf(amax, __shfl_xor_sync(0xffffffffu, amax, o));
            pmax = fmaxf(pmax, __shfl_xor_sync(0xffffffffu, pmax, o));
        }

        float ea[16];
        float sa = 0.f, sp = 0.f, dt = 0.f;
#pragma unroll
        for (int m = 0; m < 16; ++m) {
            ea[m] = __expf(a[m] - amax);
            float ep = __expf(p[m] - pmax);
            sa += ea[m];
            sp += ep;
            dt += ea[m] * ep;
        }
#pragma unroll
        for (int o = 16; o; o >>= 1) {
            sa += __shfl_xor_sync(0xffffffffu, sa, o);
            sp += __shfl_xor_sync(0xffffffffu, sp, o);
            dt += __shfl_xor_sync(0xffffffffu, dt, o);
        }

        const float inv_sa = 1.f / sa;
        if (lane == 0) {
            g_sim[row]    = dt / (sa * sp);
            g_amax[row]   = amax;
            g_ascale[row] = inv_sa;
        }
#pragma unroll
        for (int m = 0; m < 16; ++m) csum[m] += ea[m] * inv_sa;
    }

    // Stage per-warp column partials to shared (unique addresses, no atomics),
    // then combine across the block's 8 warps and write one partial row.
    float4* srow = reinterpret_cast<float4*>(sbuf[w]);
#pragma unroll
    for (int k = 0; k < 4; ++k)
        srow[lane + 32 * k] =
            make_float4(csum[4 * k], csum[4 * k + 1], csum[4 * k + 2], csum[4 * k + 3]);
    __syncthreads();
    for (int c = threadIdx.x; c < NCOLS; c += T1) {
        float s = 0.f;
#pragma unroll
        for (int ww = 0; ww < T1 / 32; ++ww) s += sbuf[ww][c];
        g_part[blockIdx.x * NCOLS + c] = s;
    }
}

// ---------------------------------------------------------------------------
// Pass 2: reduce 256 partial rows -> g_colsum. One warp per column.
// ---------------------------------------------------------------------------
__global__ void scan_colsum() {
    const int c    = blockIdx.x;
    const int lane = threadIdx.x;
    float s = 0.f;
#pragma unroll 4
    for (int pb = lane; pb < NB1; pb += 32) s += g_part[pb * NCOLS + c];
#pragma unroll
    for (int o = 16; o; o >>= 1) s += __shfl_xor_sync(0xffffffffu, s, o);
    if (lane == 0) g_colsum[c] = s;
}

// ---------------------------------------------------------------------------
// Pass 3: t[i] = (1/sa_i) * sum_j exp(a_ij - amax_i) * sim[512*(i&127)+j]
// (tile(sim, n).reshape(b, n) identity). sim slices are L2-resident.
// ---------------------------------------------------------------------------
__global__ __launch_bounds__(T3) void scan_pass3(const float* __restrict__ A) {
    const int lane = threadIdx.x & 31;
    const int w    = threadIdx.x >> 5;
    const int wg   = blockIdx.x * (T3 >> 5) + w;
    const float4* s4all = reinterpret_cast<const float4*>(g_sim);

    for (int it = 0; it < RPW3; ++it) {
        const int row   = wg + it * W3;
        const int base4 = (row & 127) << 7;   // (row&127)*512 floats / 4
        const float amax = g_amax[row];
        const float asc  = g_ascale[row];
        const float4* a4 = reinterpret_cast<const float4*>(A) + (size_t)row * (NCOLS / 4);

        float dt = 0.f;
#pragma unroll
        for (int k = 0; k < 4; ++k) {
            float4 a = a4[lane + 32 * k];
            float4 s = s4all[base4 + lane + 32 * k];
            dt += __expf(a.x - amax) * s.x
                + __expf(a.y - amax) * s.y
                + __expf(a.z - amax) * s.z
                + __expf(a.w - amax) * s.w;
        }
#pragma unroll
        for (int o = 16; o; o >>= 1) dt += __shfl_xor_sync(0xffffffffu, dt, o);
        if (lane == 0) g_t[row] = dt * asc;
    }
}

// ---------------------------------------------------------------------------
// Final: all scalar reductions in one block with double accumulators.
// ---------------------------------------------------------------------------
__global__ __launch_bounds__(1024) void scan_final(float* __restrict__ out) {
    const int tid = threadIdx.x;
    double cacc = 0.0, s2 = 0.0, t3 = 0.0, eacc = 0.0;

    for (int i = tid; i < B_ROWS; i += 1024) {
        float sim = g_sim[i];
        float lg  = logf(sim);
        cacc += (double)fmaxf(lg, -100.f);
        s2   += (double)(fmaxf(sim, EPSF) * fmaxf(lg, EPSF));
        float t  = g_t[i];
        float lt = logf(t);
        t3   += (double)(fmaxf(t, EPSF) * fmaxf(lt, EPSF));
    }
    if (tid < NCOLS) {
        float pp = g_colsum[tid] * (1.f / (float)B_ROWS);
        float pc = fmaxf(pp, EPSF);
        eacc = (double)(pc * logf(pc));
    }

    __shared__ double sh[4][32];
    double v0 = cacc, v1 = s2, v2 = t3, v3 = eacc;
#pragma unroll
    for (int o = 16; o; o >>= 1) {
        v0 += __shfl_xor_sync(0xffffffffu, v0, o);
        v1 += __shfl_xor_sync(0xffffffffu, v1, o);
        v2 += __shfl_xor_sync(0xffffffffu, v2, o);
        v3 += __shfl_xor_sync(0xffffffffu, v3, o);
    }
    const int lane = tid & 31, wid = tid >> 5;
    if (lane == 0) { sh[0][wid] = v0; sh[1][wid] = v1; sh[2][wid] = v2; sh[3][wid] = v3; }
    __syncthreads();
    if (wid == 0) {
        double r0 = sh[0][lane], r1 = sh[1][lane], r2 = sh[2][lane], r3 = sh[3][lane];
#pragma unroll
        for (int o = 16; o; o >>= 1) {
            r0 += __shfl_xor_sync(0xffffffffu, r0, o);
            r1 += __shfl_xor_sync(0xffffffffu, r1, o);
            r2 += __shfl_xor_sync(0xffffffffu, r2, o);
            r3 += __shfl_xor_sync(0xffffffffu, r3, o);
        }
        if (lane == 0) {
            double consistency = -(r0 / (double)B_ROWS);
            double entropy     = -r3;
            double second      = r1;
            double third       = r2 / (double)NCOLS;
            double third_w     = 0.5 / sqrt((double)NCOLS);
            double diff_w      = 0.25 / (double)NCOLS;
            double total = consistency - 2.0 * entropy + diff_w * second - third_w * third;
            out[0] = (float)total;
            out[1] = (float)consistency;
            out[2] = (float)entropy;
            out[3] = (float)second;
            out[4] = (float)third;
        }
    }
}

extern "C" void kernel_launch(void* const* d_in, const int* in_sizes, int n_in,
                              void* d_out, int out_size) {
    const float* A = (const float*)d_in[0];   // anchors  [65536, 512]
    const float* P = (const float*)d_in[1];   // neighbors [65536, 512]
    float* out = (float*)d_out;

    scan_pass1<<<NB1, T1>>>(A, P);
    scan_colsum<<<NCOLS, 32>>>();
    scan_pass3<<<NB3, T3>>>(A);
    scan_final<<<1, 1024>>>(out);
}

// round 2
// speedup vs baseline: 2.2154x; 2.2154x over previous
#include <cuda_runtime.h>
#include <math.h>

#define B_ROWS 65536
#define NCOLS  512
#define EPSF   1e-8f

// pass1: 512 blocks x 256 threads = 4096 warps, 16 rows/warp
#define NB1 512
#define T1  256
#define W1  (NB1 * (T1 / 32))
#define RPW1 (B_ROWS / W1)

// pass3: 512 blocks x 256 threads = 4096 warps, 16 rows/warp
#define NB3 512
#define T3  256
#define W3  (NB3 * (T3 / 32))
#define RPW3 (B_ROWS / W3)

__device__ float  g_sim[B_ROWS];
__device__ float  g_amax[B_ROWS];
__device__ float  g_ascale[B_ROWS];      // 1 / sum(exp(a - amax))
__device__ float  g_part[NB1 * NCOLS];   // per-block column partial sums
__device__ float  g_colsum[NCOLS];
__device__ double g_p1c[NB1];            // per-block sum of max(log sim, -100)
__device__ double g_p1s[NB1];            // per-block sum of max(sim,eps)*max(log sim,eps)
__device__ double g_p3[NB3];             // per-block sum of max(t,eps)*max(log t,eps)

// ---------------------------------------------------------------------------
// Pass 1: per-row softmax of anchors & neighbors, sim = <a_prob, p_prob>,
// per-block column-sum partials of a_prob, and per-block scalar partials of
// the consistency / second-order terms. One warp per row, float4 loads.
// ---------------------------------------------------------------------------
__global__ __launch_bounds__(T1) void scan_pass1(const float* __restrict__ A,
                                                 const float* __restrict__ P) {
    __shared__ float  sbuf[T1 / 32][NCOLS];
    __shared__ double shc[T1 / 32], shs[T1 / 32];
    const int lane = threadIdx.x & 31;
    const int w    = threadIdx.x >> 5;
    const int wg   = blockIdx.x * (T1 >> 5) + w;

    float csum[16];
#pragma unroll
    for (int m = 0; m < 16; ++m) csum[m] = 0.f;
    double cacc = 0.0, sacc = 0.0;

    for (int it = 0; it < RPW1; ++it) {
        const int row = wg + it * W1;
        const float4* a4 = reinterpret_cast<const float4*>(A) + (size_t)row * (NCOLS / 4);
        const float4* p4 = reinterpret_cast<const float4*>(P) + (size_t)row * (NCOLS / 4);

        float a[16], p[16];
#pragma unroll
        for (int k = 0; k < 4; ++k) {
            float4 v = a4[lane + 32 * k];
            a[4 * k + 0] = v.x; a[4 * k + 1] = v.y; a[4 * k + 2] = v.z; a[4 * k + 3] = v.w;
            float4 u = p4[lane + 32 * k];
            p[4 * k + 0] = u.x; p[4 * k + 1] = u.y; p[4 * k + 2] = u.z; p[4 * k + 3] = u.w;
        }

        float amax = a[0], pmax = p[0];
#pragma unroll
        for (int m = 1; m < 16; ++m) {
            amax = fmaxf(amax, a[m]);
            pmax = fmaxf(pmax, p[m]);
        }
#pragma unroll
        for (int o = 16; o; o >>= 1) {
            amax = fmaxf(amax, __shfl_xor_sync(0xffffffffu, amax, o));
            pmax = fmaxf(pmax, __shfl_xor_sync(0xffffffffu, pmax, o));
        }

        float ea[16];
        float sa = 0.f, sp = 0.f, dt = 0.f;
#pragma unroll
        for (int m = 0; m < 16; ++m) {
            ea[m] = __expf(a[m] - amax);
            float ep = __expf(p[m] - pmax);
            sa += ea[m];
            sp += ep;
            dt += ea[m] * ep;
        }
#pragma unroll
        for (int o = 16; o; o >>= 1) {
            sa += __shfl_xor_sync(0xffffffffu, sa, o);
            sp += __shfl_xor_sync(0xffffffffu, sp, o);
            dt += __shfl_xor_sync(0xffffffffu, dt, o);
        }

        const float inv_sa = 1.f / sa;
        if (lane == 0) {
            const float sim = dt / (sa * sp);
            g_sim[row]    = sim;
            g_amax[row]   = amax;
            g_ascale[row] = inv_sa;
            const float lg = logf(sim);
            cacc += (double)fmaxf(lg, -100.f);
            sacc += (double)(fmaxf(sim, EPSF) * fmaxf(lg, EPSF));
        }
#pragma unroll
        for (int m = 0; m < 16; ++m) csum[m] += ea[m] * inv_sa;
    }

    // per-warp column partials -> shared -> one partial row per block
    float4* srow = reinterpret_cast<float4*>(sbuf[w]);
#pragma unroll
    for (int k = 0; k < 4; ++k)
        srow[lane + 32 * k] =
            make_float4(csum[4 * k], csum[4 * k + 1], csum[4 * k + 2], csum[4 * k + 3]);
    if (lane == 0) { shc[w] = cacc; shs[w] = sacc; }
    __syncthreads();
    for (int c = threadIdx.x; c < NCOLS; c += T1) {
        float s = 0.f;
#pragma unroll
        for (int ww = 0; ww < T1 / 32; ++ww) s += sbuf[ww][c];
        g_part[blockIdx.x * NCOLS + c] = s;
    }
    if (threadIdx.x == 0) {
        double c0 = 0.0, s0 = 0.0;
#pragma unroll
        for (int ww = 0; ww < T1 / 32; ++ww) { c0 += shc[ww]; s0 += shs[ww]; }
        g_p1c[blockIdx.x] = c0;
        g_p1s[blockIdx.x] = s0;
    }
}

// ---------------------------------------------------------------------------
// Pass 2: reduce NB1 partial rows -> g_colsum. One warp per column.
// ---------------------------------------------------------------------------
__global__ void scan_colsum() {
    const int c    = blockIdx.x;
    const int lane = threadIdx.x;
    float s = 0.f;
#pragma unroll 4
    for (int pb = lane; pb < NB1; pb += 32) s += g_part[pb * NCOLS + c];
#pragma unroll
    for (int o = 16; o; o >>= 1) s += __shfl_xor_sync(0xffffffffu, s, o);
    if (lane == 0) g_colsum[c] = s;
}

// ---------------------------------------------------------------------------
// Pass 3: t[i] = (1/sa_i) * sum_j exp(a_ij - amax_i) * sim[512*(i&127)+j]
// (tile(sim,n).reshape(b,n) identity; sim slices are L2-resident), and
// per-block partial of the third-order scalar term.
// ---------------------------------------------------------------------------
__global__ __launch_bounds__(T3) void scan_pass3(const float* __restrict__ A) {
    __shared__ double sht[T3 / 32];
    const int lane = threadIdx.x & 31;
    const int w    = threadIdx.x >> 5;
    const int wg   = blockIdx.x * (T3 >> 5) + w;
    const float4* s4all = reinterpret_cast<const float4*>(g_sim);

    double tacc = 0.0;
    for (int it = 0; it < RPW3; ++it) {
        const int row   = wg + it * W3;
        const int base4 = (row & 127) << 7;   // (row&127)*512/4
        const float amax = g_amax[row];
        const float asc  = g_ascale[row];
        const float4* a4 = reinterpret_cast<const float4*>(A) + (size_t)row * (NCOLS / 4);

        float dt = 0.f;
#pragma unroll
        for (int k = 0; k < 4; ++k) {
            float4 a = a4[lane + 32 * k];
            float4 s = s4all[base4 + lane + 32 * k];
            dt += __expf(a.x - amax) * s.x
                + __expf(a.y - amax) * s.y
                + __expf(a.z - amax) * s.z
                + __expf(a.w - amax) * s.w;
        }
#pragma unroll
        for (int o = 16; o; o >>= 1) dt += __shfl_xor_sync(0xffffffffu, dt, o);
        if (lane == 0) {
            const float t  = dt * asc;
            const float lt = logf(t);
            tacc += (double)(fmaxf(t, EPSF) * fmaxf(lt, EPSF));
        }
    }
    if (lane == 0) sht[w] = tacc;
    __syncthreads();
    if (threadIdx.x == 0) {
        double t0 = 0.0;
#pragma unroll
        for (int ww = 0; ww < T3 / 32; ++ww) t0 += sht[ww];
        g_p3[blockIdx.x] = t0;
    }
}

// ---------------------------------------------------------------------------
// Final: reduce the small partial arrays (<= 512 each) + column entropy.
// ---------------------------------------------------------------------------
__global__ __launch_bounds__(1024) void scan_final(float* __restrict__ out) {
    const int tid = threadIdx.x;
    double cacc = 0.0, s2 = 0.0, t3 = 0.0, eacc = 0.0;

    for (int i = tid; i < NB1; i += 1024) { cacc += g_p1c[i]; s2 += g_p1s[i]; }
    for (int i = tid; i < NB3; i += 1024) t3 += g_p3[i];
    if (tid < NCOLS) {
        float pp = g_colsum[tid] * (1.f / (float)B_ROWS);
        float pc = fmaxf(pp, EPSF);
        eacc = (double)(pc * logf(pc));
    }

    __shared__ double sh[4][32];
    double v0 = cacc, v1 = s2, v2 = t3, v3 = eacc;
#pragma unroll
    for (int o = 16; o; o >>= 1) {
        v0 += __shfl_xor_sync(0xffffffffu, v0, o);
        v1 += __shfl_xor_sync(0xffffffffu, v1, o);
        v2 += __shfl_xor_sync(0xffffffffu, v2, o);
        v3 += __shfl_xor_sync(0xffffffffu, v3, o);
    }
    const int lane = tid & 31, wid = tid >> 5;
    if (lane == 0) { sh[0][wid] = v0; sh[1][wid] = v1; sh[2][wid] = v2; sh[3][wid] = v3; }
    __syncthreads();
    if (wid == 0) {
        double r0 = sh[0][lane], r1 = sh[1][lane], r2 = sh[2][lane], r3 = sh[3][lane];
#pragma unroll
        for (int o = 16; o; o >>= 1) {
            r0 += __shfl_xor_sync(0xffffffffu, r0, o);
            r1 += __shfl_xor_sync(0xffffffffu, r1, o);
            r2 += __shfl_xor_sync(0xffffffffu, r2, o);
            r3 += __shfl_xor_sync(0xffffffffu, r3, o);
        }
        if (lane == 0) {
            double consistency = -(r0 / (double)B_ROWS);
            double entropy     = -r3;
            double second      = r1;
            double third       = r2 / (double)NCOLS;
            double third_w     = 0.5 / sqrt((double)NCOLS);
            double diff_w      = 0.25 / (double)NCOLS;
            double total = consistency - 2.0 * entropy + diff_w * second - third_w * third;
            out[0] = (float)total;
            out[1] = (float)consistency;
            out[2] = (float)entropy;
            out[3] = (float)second;
            out[4] = (float)third;
        }
    }
}

extern "C" void kernel_launch(void* const* d_in, const int* in_sizes, int n_in,
                              void* d_out, int out_size) {
    const float* A = (const float*)d_in[0];   // anchors   [65536, 512]
    const float* P = (const float*)d_in[1];   // neighbors [65536, 512]
    float* out = (float*)d_out;

    scan_pass1<<<NB1, T1>>>(A, P);
    scan_colsum<<<NCOLS, 32>>>();
    scan_pass3<<<NB3, T3>>>(A);
    scan_final<<<1, 1024>>>(out);
}

// round 3
// speedup vs baseline: 2.3892x; 1.0784x over previous
#include <cuda_runtime.h>
#include <math.h>

#define B_ROWS 65536
#define NCOLS  512
#define EPSF   1e-8f

// pass1: 512 blocks x 256 threads = 4096 warps, 16 rows/warp
#define NB1 512
#define T1  256
#define W1  (NB1 * (T1 / 32))
#define RPW1 (B_ROWS / W1)

// pass3: 512 blocks (== NCOLS) x 256 threads = 4096 warps, 16 rows/warp
#define NB3 512
#define T3  256
#define W3  (NB3 * (T3 / 32))
#define RPW3 (B_ROWS / W3)

__device__ float  g_sim[B_ROWS];
__device__ float  g_amax[B_ROWS];
__device__ float  g_ascale[B_ROWS];      // 1 / sum(exp(a - amax))
__device__ float  g_part[NB1 * NCOLS];   // per-block column partial sums
__device__ double g_p1c[NB1];            // per-block sum of max(log sim, -100)
__device__ double g_p1s[NB1];            // per-block sum of max(sim,eps)*max(log sim,eps)
__device__ double g_p3[NB3];             // per-block sum of max(t,eps)*max(log t,eps)
__device__ double g_epart[NCOLS];        // per-column pc*log(pc)
__device__ unsigned int g_done;          // ticket counter (zero-init; reset each run)

// ---------------------------------------------------------------------------
// Pass 1: per-row softmax of anchors & neighbors, sim = <a_prob, p_prob>,
// per-block column-sum partials of a_prob, and per-block scalar partials of
// the consistency / second-order terms. One warp per row, float4 loads.
// ---------------------------------------------------------------------------
__global__ __launch_bounds__(T1) void scan_pass1(const float* __restrict__ A,
                                                 const float* __restrict__ P) {
    __shared__ float  sbuf[T1 / 32][NCOLS];
    __shared__ double shc[T1 / 32], shs[T1 / 32];
    const int lane = threadIdx.x & 31;
    const int w    = threadIdx.x >> 5;
    const int wg   = blockIdx.x * (T1 >> 5) + w;

    float csum[16];
#pragma unroll
    for (int m = 0; m < 16; ++m) csum[m] = 0.f;
    double cacc = 0.0, sacc = 0.0;

    for (int it = 0; it < RPW1; ++it) {
        const int row = wg + it * W1;
        const float4* a4 = reinterpret_cast<const float4*>(A) + (size_t)row * (NCOLS / 4);
        const float4* p4 = reinterpret_cast<const float4*>(P) + (size_t)row * (NCOLS / 4);

        float a[16], p[16];
#pragma unroll
        for (int k = 0; k < 4; ++k) {
            float4 v = a4[lane + 32 * k];
            a[4 * k + 0] = v.x; a[4 * k + 1] = v.y; a[4 * k + 2] = v.z; a[4 * k + 3] = v.w;
            float4 u = p4[lane + 32 * k];
            p[4 * k + 0] = u.x; p[4 * k + 1] = u.y; p[4 * k + 2] = u.z; p[4 * k + 3] = u.w;
        }

        float amax = a[0], pmax = p[0];
#pragma unroll
        for (int m = 1; m < 16; ++m) {
            amax = fmaxf(amax, a[m]);
            pmax = fmaxf(pmax, p[m]);
        }
#pragma unroll
        for (int o = 16; o; o >>= 1) {
            amax = fmaxf(amax, __shfl_xor_sync(0xffffffffu, amax, o));
            pmax = fmaxf(pmax, __shfl_xor_sync(0xffffffffu, pmax, o));
        }

        float ea[16];
        float sa = 0.f, sp = 0.f, dt = 0.f;
#pragma unroll
        for (int m = 0; m < 16; ++m) {
            ea[m] = __expf(a[m] - amax);
            float ep = __expf(p[m] - pmax);
            sa += ea[m];
            sp += ep;
            dt += ea[m] * ep;
        }
#pragma unroll
        for (int o = 16; o; o >>= 1) {
            sa += __shfl_xor_sync(0xffffffffu, sa, o);
            sp += __shfl_xor_sync(0xffffffffu, sp, o);
            dt += __shfl_xor_sync(0xffffffffu, dt, o);
        }

        const float inv_sa = 1.f / sa;
        if (lane == 0) {
            const float sim = dt / (sa * sp);
            g_sim[row]    = sim;
            g_amax[row]   = amax;
            g_ascale[row] = inv_sa;
            const float lg = logf(sim);
            cacc += (double)fmaxf(lg, -100.f);
            sacc += (double)(fmaxf(sim, EPSF) * fmaxf(lg, EPSF));
        }
#pragma unroll
        for (int m = 0; m < 16; ++m) csum[m] += ea[m] * inv_sa;
    }

    // per-warp column partials -> shared -> one partial row per block
    float4* srow = reinterpret_cast<float4*>(sbuf[w]);
#pragma unroll
    for (int k = 0; k < 4; ++k)
        srow[lane + 32 * k] =
            make_float4(csum[4 * k], csum[4 * k + 1], csum[4 * k + 2], csum[4 * k + 3]);
    if (lane == 0) { shc[w] = cacc; shs[w] = sacc; }
    __syncthreads();
    for (int c = threadIdx.x; c < NCOLS; c += T1) {
        float s = 0.f;
#pragma unroll
        for (int ww = 0; ww < T1 / 32; ++ww) s += sbuf[ww][c];
        g_part[blockIdx.x * NCOLS + c] = s;
    }
    if (threadIdx.x == 0) {
        double c0 = 0.0, s0 = 0.0;
#pragma unroll
        for (int ww = 0; ww < T1 / 32; ++ww) { c0 += shc[ww]; s0 += shs[ww]; }
        g_p1c[blockIdx.x] = c0;
        g_p1s[blockIdx.x] = s0;
    }
}

// ---------------------------------------------------------------------------
// Pass 3 (fused): column-entropy partial for column blockIdx.x, then
// t[i] = (1/sa_i) * sum_j exp(a_ij - amax_i) * sim[512*(i&127)+j]
// (tile(sim,n).reshape(b,n) identity; sim slices L2-resident),
// then the LAST block to finish reduces everything and writes the output.
// ---------------------------------------------------------------------------
__global__ __launch_bounds__(T3) void scan_pass3_final(const float* __restrict__ A,
                                                       float* __restrict__ out) {
    __shared__ double shd[T3 / 32];
    __shared__ float  shf[T3 / 32];
    const int lane = threadIdx.x & 31;
    const int w    = threadIdx.x >> 5;
    const int wg   = blockIdx.x * (T3 >> 5) + w;

    // --- Phase A: colsum of column b over NB1 pass1 partials -> entropy term
    {
        const int b = blockIdx.x;   // NB3 == NCOLS
        float s = 0.f;
#pragma unroll
        for (int k = 0; k < NB1 / T3; ++k)
            s += g_part[(threadIdx.x + k * T3) * NCOLS + b];
#pragma unroll
        for (int o = 16; o; o >>= 1) s += __shfl_xor_sync(0xffffffffu, s, o);
        if (lane == 0) shf[w] = s;
        __syncthreads();
        if (threadIdx.x == 0) {
            float cs = 0.f;
#pragma unroll
            for (int ww = 0; ww < T3 / 32; ++ww) cs += shf[ww];
            float pp = cs * (1.f / (float)B_ROWS);
            float pc = fmaxf(pp, EPSF);
            g_epart[b] = (double)(pc * logf(pc));
        }
    }
    __syncthreads();

    // --- Phase B: third-order pass
    const float4* s4all = reinterpret_cast<const float4*>(g_sim);
    double tacc = 0.0;
    for (int it = 0; it < RPW3; ++it) {
        const int row   = wg + it * W3;
        const int base4 = (row & 127) << 7;   // (row&127)*512/4
        const float amax = g_amax[row];
        const float asc  = g_ascale[row];
        const float4* a4 = reinterpret_cast<const float4*>(A) + (size_t)row * (NCOLS / 4);

        float dt = 0.f;
#pragma unroll
        for (int k = 0; k < 4; ++k) {
            float4 a = a4[lane + 32 * k];
            float4 s = s4all[base4 + lane + 32 * k];
            dt += __expf(a.x - amax) * s.x
                + __expf(a.y - amax) * s.y
                + __expf(a.z - amax) * s.z
                + __expf(a.w - amax) * s.w;
        }
#pragma unroll
        for (int o = 16; o; o >>= 1) dt += __shfl_xor_sync(0xffffffffu, dt, o);
        if (lane == 0) {
            const float t  = dt * asc;
            const float lt = logf(t);
            tacc += (double)(fmaxf(t, EPSF) * fmaxf(lt, EPSF));
        }
    }
    if (lane == 0) shd[w] = tacc;
    __syncthreads();
    if (threadIdx.x == 0) {
        double t0 = 0.0;
#pragma unroll
        for (int ww = 0; ww < T3 / 32; ++ww) t0 += shd[ww];
        g_p3[blockIdx.x] = t0;
    }

    // --- Phase C: last block finishes the reduction
    __shared__ bool is_last;
    __threadfence();
    if (threadIdx.x == 0) {
        unsigned int t = atomicAdd(&g_done, 1u);
        is_last = (t == NB3 - 1);
    }
    __syncthreads();
    if (!is_last) return;
    __threadfence();

    double cacc = 0.0, s2 = 0.0, t3 = 0.0, eacc = 0.0;
#pragma unroll
    for (int k = 0; k < NB1 / T3; ++k) {
        const int i = threadIdx.x + k * T3;
        cacc += g_p1c[i];
        s2   += g_p1s[i];
    }
#pragma unroll
    for (int k = 0; k < NB3 / T3; ++k) t3 += g_p3[threadIdx.x + k * T3];
#pragma unroll
    for (int k = 0; k < NCOLS / T3; ++k) eacc += g_epart[threadIdx.x + k * T3];

    __shared__ double sh[4][T3 / 32];
    double v0 = cacc, v1 = s2, v2 = t3, v3 = eacc;
#pragma unroll
    for (int o = 16; o; o >>= 1) {
        v0 += __shfl_xor_sync(0xffffffffu, v0, o);
        v1 += __shfl_xor_sync(0xffffffffu, v1, o);
        v2 += __shfl_xor_sync(0xffffffffu, v2, o);
        v3 += __shfl_xor_sync(0xffffffffu, v3, o);
    }
    if (lane == 0) { sh[0][w] = v0; sh[1][w] = v1; sh[2][w] = v2; sh[3][w] = v3; }
    __syncthreads();
    if (threadIdx.x == 0) {
        double r0 = 0.0, r1 = 0.0, r2 = 0.0, r3 = 0.0;
#pragma unroll
        for (int ww = 0; ww < T3 / 32; ++ww) {
            r0 += sh[0][ww]; r1 += sh[1][ww]; r2 += sh[2][ww]; r3 += sh[3][ww];
        }
        double consistency = -(r0 / (double)B_ROWS);
        double entropy     = -r3;
        double second      = r1;
        double third       = r2 / (double)NCOLS;
        double third_w     = 0.5 / sqrt((double)NCOLS);
        double diff_w      = 0.25 / (double)NCOLS;
        double total = consistency - 2.0 * entropy + diff_w * second - third_w * third;
        out[0] = (float)total;
        out[1] = (float)consistency;
        out[2] = (float)entropy;
        out[3] = (float)second;
        out[4] = (float)third;
        g_done = 0u;   // reset for the next (graph-replayed) launch
    }
}

extern "C" void kernel_launch(void* const* d_in, const int* in_sizes, int n_in,
                              void* d_out, int out_size) {
    const float* A = (const float*)d_in[0];   // anchors   [65536, 512]
    const float* P = (const float*)d_in[1];   // neighbors [65536, 512]
    float* out = (float*)d_out;

    scan_pass1<<<NB1, T1>>>(A, P);
    scan_pass3_final<<<NB3, T3>>>(A, out);
}